// round 1
// baseline (speedup 1.0000x reference)
#include <cuda_runtime.h>

#define TBLOCK 256
#define ITEMS  4
#define NFILT  11
#define NCOLS  262144
#define NROWS  128
#define WIN    (ITEMS + 12)   // 16 complex = 8 float4, aligned window [c0-6, c0+9]

typedef unsigned long long u64;

__device__ __forceinline__ u64 pack2(float lo, float hi) {
    u64 r;
    asm("mov.b64 %0, {%1, %2};" : "=l"(r) : "f"(lo), "f"(hi));
    return r;
}
__device__ __forceinline__ void unpack2(u64 v, float& lo, float& hi) {
    asm("mov.b64 {%0, %1}, %2;" : "=f"(lo), "=f"(hi) : "l"(v));
}
__device__ __forceinline__ u64 fma2(u64 a, u64 b, u64 c) {
    u64 d;
    asm("fma.rn.f32x2 %0, %1, %2, %3;" : "=l"(d) : "l"(a), "l"(b), "l"(c));
    return d;
}

__global__ void __launch_bounds__(TBLOCK) fir_complex_kernel(
    const float2* __restrict__ X, const float* __restrict__ phi,
    float2* __restrict__ Y)
{
    const int row = blockIdx.y;
    const int c0  = (blockIdx.x * TBLOCK + threadIdx.x) * ITEMS;
    const float2* __restrict__ xrow = X + (size_t)row * NCOLS;
    float2* __restrict__ yrow       = Y + (size_t)row * NCOLS;

    // Coefficients: phi[k] = (wr, wi) contiguous. A_k = (wr,wi), B_k = (wi,wr).
    u64 A[NFILT], B[NFILT];
#pragma unroll
    for (int k = 0; k < NFILT; k++) {
        float2 w = __ldg(((const float2*)phi) + k);
        A[k] = pack2(w.x, w.y);
        B[k] = pack2(w.y, w.x);
    }

    // Load window: complex columns [c0-6, c0+9], j = local index 0..15.
    float2 xv[WIN];
    if (c0 >= 6 && c0 + (ITEMS + 5) < NCOLS) {
        const float4* p = (const float4*)(xrow + (c0 - 6));
#pragma unroll
        for (int j = 0; j < WIN / 2; j++) {
            float4 v = __ldg(p + j);
            xv[2*j]     = make_float2(v.x, v.y);
            xv[2*j + 1] = make_float2(v.z, v.w);
        }
    } else {
        // Row edge: SAME padding -> zeros outside [0, NCOLS)
#pragma unroll
        for (int j = 0; j < WIN; j++) {
            int idx = c0 - 6 + j;
            xv[j] = (idx >= 0 && idx < NCOLS) ? xrow[idx] : make_float2(0.f, 0.f);
        }
    }

    // accA[i] = sum_k xr * (wr, wi);  accB[i] = sum_k xi * (wi, wr)
    // output i uses xv[i + k + 1], k = 0..10
    u64 accA[ITEMS], accB[ITEMS];
#pragma unroll
    for (int i = 0; i < ITEMS; i++) { accA[i] = 0ull; accB[i] = 0ull; }

#pragma unroll
    for (int j = 1; j <= ITEMS + 10; j++) {
        u64 xrr = pack2(xv[j].x, xv[j].x);
        u64 xii = pack2(xv[j].y, xv[j].y);
#pragma unroll
        for (int i = 0; i < ITEMS; i++) {
            int k = j - 1 - i;                 // compile-time constant after unroll
            if (k >= 0 && k < NFILT) {
                accA[i] = fma2(xrr, A[k], accA[i]);
                accB[i] = fma2(xii, B[k], accB[i]);
            }
        }
    }

    // result = (accA.lo - accB.lo, accA.hi + accB.hi) via one packed FMA
    const u64 CNEG = pack2(-1.0f, 1.0f);
    float4 o[ITEMS / 2];
#pragma unroll
    for (int i = 0; i < ITEMS; i++) {
        u64 r = fma2(accB[i], CNEG, accA[i]);
        float re, im;
        unpack2(r, re, im);
        if (i & 1) { o[i / 2].z = re; o[i / 2].w = im; }
        else       { o[i / 2].x = re; o[i / 2].y = im; }
    }
    float4* yo = (float4*)(yrow + c0);
#pragma unroll
    for (int q = 0; q < ITEMS / 2; q++) yo[q] = o[q];
}

extern "C" void kernel_launch(void* const* d_in, const int* in_sizes, int n_in,
                              void* d_out, int out_size)
{
    const float2* X   = (const float2*)d_in[0];
    const float*  phi = (const float*)d_in[1];
    float2*       Y   = (float2*)d_out;

    dim3 grid(NCOLS / (TBLOCK * ITEMS), NROWS);
    fir_complex_kernel<<<grid, TBLOCK>>>(X, phi, Y);
}

// round 2
// speedup vs baseline: 1.0123x; 1.0123x over previous
#include <cuda_runtime.h>

#define TBLOCK   256
#define ITEMS    4
#define NFILT    11
#define NCOLS    262144
#define NROWS    128
#define TILE     (TBLOCK * ITEMS)        // 1024 outputs per block
#define HALO_L   8                       // aligned left apron (need 5)
#define HALO_R   8                       // right apron (need 8)
#define SWIDTH   (TILE + HALO_L + HALO_R)  // 1040 complex staged

typedef unsigned long long u64;

__device__ __forceinline__ u64 pack2(float lo, float hi) {
    u64 r;
    asm("mov.b64 %0, {%1, %2};" : "=l"(r) : "f"(lo), "f"(hi));
    return r;
}
__device__ __forceinline__ void unpack2(u64 v, float& lo, float& hi) {
    asm("mov.b64 {%0, %1}, %2;" : "=f"(lo), "=f"(hi) : "l"(v));
}
__device__ __forceinline__ u64 fma2(u64 a, u64 b, u64 c) {
    u64 d;
    asm("fma.rn.f32x2 %0, %1, %2, %3;" : "=l"(d) : "l"(a), "l"(b), "l"(c));
    return d;
}

__global__ void __launch_bounds__(TBLOCK) fir_complex_smem_kernel(
    const float2* __restrict__ X, const float* __restrict__ phi,
    float2* __restrict__ Y)
{
    __shared__ float s_re[SWIDTH + 8];
    __shared__ float s_im[SWIDTH + 8];

    const int tid   = threadIdx.x;
    const int row   = blockIdx.y;
    const int tile0 = blockIdx.x * TILE;
    const float2* __restrict__ xrow = X + (size_t)row * NCOLS;
    float2* __restrict__ yrow       = Y + (size_t)row * NCOLS;

    // Coefficients: A[k] = (wr_k, wi_k) — exactly phi's layout, load as u64.
    u64 A[NFILT];
#pragma unroll
    for (int k = 0; k < NFILT; k++) {
        float2 w = __ldg(((const float2*)phi) + k);
        A[k] = pack2(w.x, w.y);
    }

    // ---- Stage tile [tile0-8, tile0+1032) into SoA smem ----
    const bool interior = (tile0 >= HALO_L) && (tile0 + TILE + HALO_R <= NCOLS);
    if (interior) {
        const float4* gp = (const float4*)(xrow + (tile0 - HALO_L));  // 2 complex per float4
#pragma unroll
        for (int q = tid; q < SWIDTH / 2; q += TBLOCK) {
            float4 v = gp[q];                         // complex 2q, 2q+1
            *(float2*)(s_re + 2 * q) = make_float2(v.x, v.z);
            *(float2*)(s_im + 2 * q) = make_float2(v.y, v.w);
        }
    } else {
        for (int j = tid; j < SWIDTH; j += TBLOCK) {
            int g = tile0 - HALO_L + j;
            float2 v = (g >= 0 && g < NCOLS) ? xrow[g] : make_float2(0.f, 0.f);
            s_re[j] = v.x;
            s_im[j] = v.y;
        }
    }
    __syncthreads();

    // ---- Compute 4 outputs per thread from smem ----
    // Local window: smem index 4*tid + j, j=0..16 maps to x[c0 - 8 + j].
    // Output i (col c0+i) tap k reads x[c0+i+k-5] -> j = i + k + 3.
    float re[17], im[17];
    {
        const float4* pr = (const float4*)(s_re + 4 * tid);
        const float4* pi = (const float4*)(s_im + 4 * tid);
#pragma unroll
        for (int q = 0; q < 4; q++) {
            float4 vr = pr[q], vi = pi[q];
            re[4*q] = vr.x; re[4*q+1] = vr.y; re[4*q+2] = vr.z; re[4*q+3] = vr.w;
            im[4*q] = vi.x; im[4*q+1] = vi.y; im[4*q+2] = vi.z; im[4*q+3] = vi.w;
        }
        re[16] = s_re[4 * tid + 16];
        im[16] = s_im[4 * tid + 16];
    }

    // P[i] = sum_k (xr,xr)*A[k] = (S_rr, S_ri);  Q[i] = sum_k (xi,xi)*A[k] = (S_ir, S_ii)
    u64 P[ITEMS], Q[ITEMS];
#pragma unroll
    for (int i = 0; i < ITEMS; i++) { P[i] = 0ull; Q[i] = 0ull; }

#pragma unroll
    for (int j = 3; j <= 16; j++) {
        u64 xrr = pack2(re[j], re[j]);
        u64 xii = pack2(im[j], im[j]);
#pragma unroll
        for (int i = 0; i < ITEMS; i++) {
            int k = j - 3 - i;                 // compile-time constant after unroll
            if (k >= 0 && k < NFILT) {
                P[i] = fma2(xrr, A[k], P[i]);
                Q[i] = fma2(xii, A[k], Q[i]);
            }
        }
    }

    // out = (P.lo - Q.hi, P.hi + Q.lo)
    const int c0 = tile0 + 4 * tid;
    float4 o[ITEMS / 2];
#pragma unroll
    for (int i = 0; i < ITEMS; i++) {
        float prr, pri, qir, qii;
        unpack2(P[i], prr, pri);
        unpack2(Q[i], qir, qii);
        float ore = prr - qii;
        float oim = pri + qir;
        if (i & 1) { o[i / 2].z = ore; o[i / 2].w = oim; }
        else       { o[i / 2].x = ore; o[i / 2].y = oim; }
    }
    float4* yo = (float4*)(yrow + c0);
    yo[0] = o[0];
    yo[1] = o[1];
}

extern "C" void kernel_launch(void* const* d_in, const int* in_sizes, int n_in,
                              void* d_out, int out_size)
{
    const float2* X   = (const float2*)d_in[0];
    const float*  phi = (const float*)d_in[1];
    float2*       Y   = (float2*)d_out;

    dim3 grid(NCOLS / TILE, NROWS);
    fir_complex_smem_kernel<<<grid, TBLOCK>>>(X, phi, Y);
}